// round 2
// baseline (speedup 1.0000x reference)
#include <cuda_runtime.h>
#include <cuda_bf16.h>
#include <cstdint>

#define B_   2
#define L_   2048
#define DM_  256
#define DI_  512
#define NS_  16
#define NL_  4
#define DO_  10
#define MR_  (B_*L_)          // 4096 rows
#define NC_  64               // scan chunks
#define CL_  (L_/NC_)         // 32 per chunk

// ---------------- scratch (static device memory; no allocations) ----------------
__device__ __align__(16) float g_resid [MR_*DM_];
__device__ __align__(16) float g_hidden[MR_*DM_];
__device__ __align__(16) float g_ln    [MR_*DM_];
__device__ __align__(16) float g_lnf   [MR_*DM_];
__device__ __align__(16) float g_xz    [MR_*2*DI_];
__device__ __align__(16) float g_xc    [MR_*DI_];
__device__ __align__(16) float g_xdbl  [MR_*48];
__device__ __align__(16) float g_delta [MR_*DI_];
__device__ __align__(16) float g_yloc  [MR_*DI_];
__device__ __align__(16) float g_yg    [MR_*DI_];
__device__ __align__(16) float g_P     [B_*NC_*DI_*NS_];
__device__ __align__(16) float g_hend  [B_*NC_*DI_*NS_];
__device__ __align__(16) float g_hin   [B_*NC_*DI_*NS_];
__device__ __align__(16) float g_part  [B_*32*DM_];

__device__ __forceinline__ float fex2(float x){ float r; asm("ex2.approx.f32 %0, %1;" : "=f"(r) : "f"(x)); return r; }
__device__ __forceinline__ float fexp(float x){ return fex2(x*1.44269504f); }
__device__ __forceinline__ float f2tf(float x){ unsigned u; asm("cvt.rna.tf32.f32 %0, %1;" : "=r"(u) : "f"(x)); return __uint_as_float(u); }

// ---------------- embedding gather: residual = emb[ids] ----------------
__global__ void k_embed(const int* __restrict__ ids, const float* __restrict__ emb){
    int idx = blockIdx.x*blockDim.x + threadIdx.x;   // MR_*64 threads
    int m = idx >> 6, c = (idx & 63) << 2;
    int id = ids[m];
    float4 v = *(const float4*)(emb + (size_t)id*DM_ + c);
    *(float4*)(g_resid + (size_t)m*DM_ + c) = v;
}

// ---------------- residual add + layernorm (1 warp per row of 256) ----------------
__global__ void k_ln(const float* __restrict__ w, const float* __restrict__ b,
                     float* __restrict__ out, int add){
    int row  = blockIdx.x*8 + (threadIdx.x>>5);
    int lane = threadIdx.x & 31;
    float* res = g_resid + (size_t)row*DM_;
    float4 a0 = *(float4*)(res + lane*4);
    float4 a1 = *(float4*)(res + lane*4 + 128);
    if(add){
        const float* h = g_hidden + (size_t)row*DM_;
        float4 h0 = *(const float4*)(h + lane*4);
        float4 h1 = *(const float4*)(h + lane*4 + 128);
        a0.x+=h0.x; a0.y+=h0.y; a0.z+=h0.z; a0.w+=h0.w;
        a1.x+=h1.x; a1.y+=h1.y; a1.z+=h1.z; a1.w+=h1.w;
        *(float4*)(res + lane*4)       = a0;
        *(float4*)(res + lane*4 + 128) = a1;
    }
    float s = a0.x+a0.y+a0.z+a0.w+a1.x+a1.y+a1.z+a1.w;
    #pragma unroll
    for(int o=16;o;o>>=1) s += __shfl_xor_sync(0xffffffffu, s, o);
    float mean = s * (1.f/DM_);
    float q = 0.f;
    q += (a0.x-mean)*(a0.x-mean); q += (a0.y-mean)*(a0.y-mean);
    q += (a0.z-mean)*(a0.z-mean); q += (a0.w-mean)*(a0.w-mean);
    q += (a1.x-mean)*(a1.x-mean); q += (a1.y-mean)*(a1.y-mean);
    q += (a1.z-mean)*(a1.z-mean); q += (a1.w-mean)*(a1.w-mean);
    #pragma unroll
    for(int o=16;o;o>>=1) q += __shfl_xor_sync(0xffffffffu, q, o);
    float rs = rsqrtf(q*(1.f/DM_) + 1e-5f);
    float4 w0 = *(const float4*)(w + lane*4), w1 = *(const float4*)(w + lane*4 + 128);
    float4 b0 = *(const float4*)(b + lane*4), b1 = *(const float4*)(b + lane*4 + 128);
    float4 o0, o1;
    o0.x=(a0.x-mean)*rs*w0.x+b0.x; o0.y=(a0.y-mean)*rs*w0.y+b0.y;
    o0.z=(a0.z-mean)*rs*w0.z+b0.z; o0.w=(a0.w-mean)*rs*w0.w+b0.w;
    o1.x=(a1.x-mean)*rs*w1.x+b1.x; o1.y=(a1.y-mean)*rs*w1.y+b1.y;
    o1.z=(a1.z-mean)*rs*w1.z+b1.z; o1.w=(a1.w-mean)*rs*w1.w+b1.w;
    *(float4*)(out + (size_t)row*DM_ + lane*4)       = o0;
    *(float4*)(out + (size_t)row*DM_ + lane*4 + 128) = o1;
}

// ---------------- tf32 mma GEMM: C[M,N] = A[M,K] * W[N,K]^T ----------------
// BM=128, BN=128, BK=32, 256 threads (8 warps as 2(m) x 4(n))
__global__ void __launch_bounds__(256) k_gemm(const float* __restrict__ A,
                                              const float* __restrict__ W,
                                              float* __restrict__ C,
                                              int M, int N, int K){
    __shared__ float As[128][36];
    __shared__ float Bs[128][36];
    const int bm = blockIdx.y*128, bn = blockIdx.x*128;
    const int tid = threadIdx.x, lane = tid&31, wid = tid>>5;
    const int wm = (wid&1)*64, wn = (wid>>1)*32;
    const int g = lane>>2, t4 = lane&3;
    float acc[4][4][4];
    #pragma unroll
    for(int i=0;i<4;i++)
        #pragma unroll
        for(int j=0;j<4;j++){ acc[i][j][0]=0.f; acc[i][j][1]=0.f; acc[i][j][2]=0.f; acc[i][j][3]=0.f; }

    for(int k0=0;k0<K;k0+=32){
        #pragma unroll
        for(int i=0;i<4;i++){
            int lin = tid + i*256;
            int row = lin>>3, c4 = (lin&7)<<2;
            float4 v = *(const float4*)(A + (size_t)(bm+row)*K + k0 + c4);
            v.x=f2tf(v.x); v.y=f2tf(v.y); v.z=f2tf(v.z); v.w=f2tf(v.w);
            *(float4*)(&As[row][c4]) = v;
        }
        #pragma unroll
        for(int i=0;i<4;i++){
            int lin = tid + i*256;
            int row = lin>>3, c4 = (lin&7)<<2;
            float4 v = make_float4(0.f,0.f,0.f,0.f);
            if(bn+row < N) v = *(const float4*)(W + (size_t)(bn+row)*K + k0 + c4);
            v.x=f2tf(v.x); v.y=f2tf(v.y); v.z=f2tf(v.z); v.w=f2tf(v.w);
            *(float4*)(&Bs[row][c4]) = v;
        }
        __syncthreads();
        #pragma unroll
        for(int ks=0;ks<4;ks++){
            const int kk = ks*8;
            unsigned a[4][4], bf[4][2];
            #pragma unroll
            for(int mt=0;mt<4;mt++){
                int r0 = wm + mt*16 + g;
                a[mt][0] = __float_as_uint(As[r0  ][kk+t4  ]);
                a[mt][1] = __float_as_uint(As[r0+8][kk+t4  ]);
                a[mt][2] = __float_as_uint(As[r0  ][kk+t4+4]);
                a[mt][3] = __float_as_uint(As[r0+8][kk+t4+4]);
            }
            #pragma unroll
            for(int nt=0;nt<4;nt++){
                int c0 = wn + nt*8 + g;
                bf[nt][0] = __float_as_uint(Bs[c0][kk+t4  ]);
                bf[nt][1] = __float_as_uint(Bs[c0][kk+t4+4]);
            }
            #pragma unroll
            for(int mt=0;mt<4;mt++)
                #pragma unroll
                for(int nt=0;nt<4;nt++){
                    asm volatile("mma.sync.aligned.m16n8k8.row.col.f32.tf32.tf32.f32 "
                        "{%0,%1,%2,%3}, {%4,%5,%6,%7}, {%8,%9}, {%0,%1,%2,%3};"
                        : "+f"(acc[mt][nt][0]), "+f"(acc[mt][nt][1]),
                          "+f"(acc[mt][nt][2]), "+f"(acc[mt][nt][3])
                        : "r"(a[mt][0]),"r"(a[mt][1]),"r"(a[mt][2]),"r"(a[mt][3]),
                          "r"(bf[nt][0]),"r"(bf[nt][1]));
                }
        }
        __syncthreads();
    }
    #pragma unroll
    for(int mt=0;mt<4;mt++){
        int r0 = bm + wm + mt*16 + g;
        #pragma unroll
        for(int nt=0;nt<4;nt++){
            int c0 = bn + wn + nt*8 + t4*2;
            if(c0 < N){
                *(float2*)(C + (size_t)r0*N + c0)     = make_float2(acc[mt][nt][0], acc[mt][nt][1]);
                *(float2*)(C + (size_t)(r0+8)*N + c0) = make_float2(acc[mt][nt][2], acc[mt][nt][3]);
            }
        }
    }
}

// ---------------- causal depthwise conv (K=4) + silu ----------------
__global__ void k_conv(const float* __restrict__ cw, const float* __restrict__ cb){
    int idx = blockIdx.x*blockDim.x + threadIdx.x;   // MR_*DI_
    int d = idx & (DI_-1);
    int m = idx >> 9;
    int l = m & (L_-1);
    float4 w = *(const float4*)(cw + d*4);
    float s = cb[d];
    const float* xm = g_xz + d;                      // row stride 2*DI_
    if(l>=3) s += xm[(size_t)(m-3)*2*DI_]*w.x;
    if(l>=2) s += xm[(size_t)(m-2)*2*DI_]*w.y;
    if(l>=1) s += xm[(size_t)(m-1)*2*DI_]*w.z;
    s += xm[(size_t)m*2*DI_]*w.w;
    float sig = 1.f/(1.f+fexp(-s));
    g_xc[idx] = s*sig;
}

// ---------------- delta = softplus(dt @ dt_w^T + dt_b) ----------------
__global__ void k_dt(const float* __restrict__ dtw, const float* __restrict__ dtb){
    __shared__ float dtr[16];
    int m = blockIdx.x;
    int d = blockIdx.y*128 + threadIdx.x;
    if(threadIdx.x < 16) dtr[threadIdx.x] = g_xdbl[(size_t)m*48 + threadIdx.x];
    __syncthreads();
    float4 w0 = *(const float4*)(dtw + d*16);
    float4 w1 = *(const float4*)(dtw + d*16 + 4);
    float4 w2 = *(const float4*)(dtw + d*16 + 8);
    float4 w3 = *(const float4*)(dtw + d*16 + 12);
    float s = dtb[d];
    s += dtr[0]*w0.x + dtr[1]*w0.y + dtr[2]*w0.z + dtr[3]*w0.w;
    s += dtr[4]*w1.x + dtr[5]*w1.y + dtr[6]*w1.z + dtr[7]*w1.w;
    s += dtr[8]*w2.x + dtr[9]*w2.y + dtr[10]*w2.z + dtr[11]*w2.w;
    s += dtr[12]*w3.x + dtr[13]*w3.y + dtr[14]*w3.z + dtr[15]*w3.w;
    float sp = (s > 20.f) ? s : log1pf(fexp(s));
    g_delta[(size_t)m*DI_ + d] = sp;
}

// ---------------- scan pass 1: chunk-local scan (h0=0), y_local, chunk decay ----------------
__global__ void __launch_bounds__(256) k_scan1(const float* __restrict__ Alog){
    int idx = blockIdx.x*256 + threadIdx.x;          // B_*NC_*DI_ = 65536
    int d = idx & (DI_-1);
    int c = (idx >> 9) & (NC_-1);
    int b = idx >> 15;
    float An[NS_];
    #pragma unroll
    for(int i=0;i<NS_/4;i++){
        float4 v = *(const float4*)(Alog + (size_t)d*NS_ + i*4);
        An[i*4+0] = -fexp(v.x)*1.44269504f;
        An[i*4+1] = -fexp(v.y)*1.44269504f;
        An[i*4+2] = -fexp(v.z)*1.44269504f;
        An[i*4+3] = -fexp(v.w)*1.44269504f;
    }
    float h[NS_];
    #pragma unroll
    for(int n=0;n<NS_;n++) h[n]=0.f;
    float S = 0.f;
    int row0 = b*L_ + c*CL_;
    #pragma unroll 4
    for(int l=0;l<CL_;l++){
        int row = row0 + l;
        float dv = g_delta[(size_t)row*DI_ + d];
        float u  = g_xc  [(size_t)row*DI_ + d];
        const float* xd = g_xdbl + (size_t)row*48;
        float4 B0=*(const float4*)(xd+16), B1=*(const float4*)(xd+20);
        float4 B2=*(const float4*)(xd+24), B3=*(const float4*)(xd+28);
        float4 C0=*(const float4*)(xd+32), C1=*(const float4*)(xd+36);
        float4 C2=*(const float4*)(xd+40), C3=*(const float4*)(xd+44);
        float Bv[16]={B0.x,B0.y,B0.z,B0.w,B1.x,B1.y,B1.z,B1.w,B2.x,B2.y,B2.z,B2.w,B3.x,B3.y,B3.z,B3.w};
        float Cv[16]={C0.x,C0.y,C0.z,C0.w,C1.x,C1.y,C1.z,C1.w,C2.x,C2.y,C2.z,C2.w,C3.x,C3.y,C3.z,C3.w};
        S += dv;
        float du = dv*u;
        float y = 0.f;
        #pragma unroll
        for(int n=0;n<NS_;n++){
            float dA = fex2(dv*An[n]);
            h[n] = fmaf(dA, h[n], du*Bv[n]);
            y = fmaf(h[n], Cv[n], y);
        }
        g_yloc[(size_t)row*DI_ + d] = y;
    }
    int ob = ((b*NC_ + c)*DI_ + d)*NS_;
    #pragma unroll
    for(int n=0;n<NS_;n++){
        g_hend[ob+n] = h[n];
        g_P[ob+n]    = fex2(S*An[n]);   // exp(A_n * sum(delta)) == chunk decay product
    }
}

// ---------------- scan pass 2: sequential combine over chunks ----------------
__global__ void k_scan2(){
    int idx = blockIdx.x*256 + threadIdx.x;          // B_*DI_*NS_ = 16384
    int base = idx & (DI_*NS_ - 1);                  // (d,n) packed
    int b = idx >> 13;
    float run = 0.f;
    for(int c=0;c<NC_;c++){
        int o = ((b*NC_ + c)*DI_)*NS_ + base;
        g_hin[o] = run;
        run = g_P[o]*run + g_hend[o];
    }
}

// ---------------- scan pass 3: correction + Dp*xc + silu(z) gate ----------------
__global__ void __launch_bounds__(256) k_scan3(const float* __restrict__ Alog,
                                               const float* __restrict__ Dp){
    int idx = blockIdx.x*256 + threadIdx.x;
    int d = idx & (DI_-1);
    int c = (idx >> 9) & (NC_-1);
    int b = idx >> 15;
    float An[NS_];
    #pragma unroll
    for(int i=0;i<NS_/4;i++){
        float4 v = *(const float4*)(Alog + (size_t)d*NS_ + i*4);
        An[i*4+0] = -fexp(v.x)*1.44269504f;
        An[i*4+1] = -fexp(v.y)*1.44269504f;
        An[i*4+2] = -fexp(v.z)*1.44269504f;
        An[i*4+3] = -fexp(v.w)*1.44269504f;
    }
    int ob = ((b*NC_ + c)*DI_ + d)*NS_;
    float gq[NS_];
    #pragma unroll
    for(int n=0;n<NS_;n++) gq[n] = g_hin[ob+n];      // prefix-product * h_in, running
    float Dd = Dp[d];
    int row0 = b*L_ + c*CL_;
    #pragma unroll 4
    for(int l=0;l<CL_;l++){
        int row = row0 + l;
        float dv = g_delta[(size_t)row*DI_ + d];
        float u  = g_xc  [(size_t)row*DI_ + d];
        float z  = g_xz  [(size_t)row*2*DI_ + DI_ + d];
        const float* xd = g_xdbl + (size_t)row*48;
        float4 C0=*(const float4*)(xd+32), C1=*(const float4*)(xd+36);
        float4 C2=*(const float4*)(xd+40), C3=*(const float4*)(xd+44);
        float Cv[16]={C0.x,C0.y,C0.z,C0.w,C1.x,C1.y,C1.z,C1.w,C2.x,C2.y,C2.z,C2.w,C3.x,C3.y,C3.z,C3.w};
        float corr = 0.f;
        #pragma unroll
        for(int n=0;n<NS_;n++){
            float dA = fex2(dv*An[n]);
            gq[n] *= dA;
            corr = fmaf(gq[n], Cv[n], corr);
        }
        float y = g_yloc[(size_t)row*DI_ + d] + corr + Dd*u;
        float sig = 1.f/(1.f+fexp(-z));
        g_yg[(size_t)row*DI_ + d] = y * z * sig;
    }
}

// ---------------- pooling + decode ----------------
__global__ void k_pool1(){
    int idx = blockIdx.x*256 + threadIdx.x;          // B_*32*DM_ = 16384
    int dm = idx & 255;
    int seg = (idx >> 8) & 31;
    int b = idx >> 13;
    float s = 0.f;
    #pragma unroll 8
    for(int j=0;j<64;j++)
        s += g_lnf[((size_t)(b*L_) + seg*64 + j)*DM_ + dm];
    g_part[idx] = s;
}

__global__ void k_pool2(const float* __restrict__ decw, const float* __restrict__ decb,
                        float* __restrict__ out){
    __shared__ float pool[DM_];
    int b = blockIdx.x;
    int tid = threadIdx.x;
    float s = 0.f;
    #pragma unroll
    for(int seg=0;seg<32;seg++) s += g_part[(b*32+seg)*256 + tid];
    pool[tid] = s * (1.f/L_);
    __syncthreads();
    if(tid < DO_){
        float o = decb[tid];
        for(int k=0;k<DM_;k++) o = fmaf(pool[k], decw[tid*DM_+k], o);
        out[b*DO_ + tid] = o;
    }
}

// ---------------- host ----------------
extern "C" void kernel_launch(void* const* d_in, const int* in_sizes, int n_in,
                              void* d_out, int out_size){
    const int*   ids   = (const int*)  d_in[0];
    const float* emb   = (const float*)d_in[1];
    const float* nw    = (const float*)d_in[2];
    const float* nb    = (const float*)d_in[3];
    const float* inw   = (const float*)d_in[4];
    const float* cw    = (const float*)d_in[5];
    const float* cb    = (const float*)d_in[6];
    const float* xpw   = (const float*)d_in[7];
    const float* dtw   = (const float*)d_in[8];
    const float* dtb   = (const float*)d_in[9];
    const float* Alog  = (const float*)d_in[10];
    const float* Dp    = (const float*)d_in[11];
    const float* outw  = (const float*)d_in[12];
    const float* nfw   = (const float*)d_in[13];
    const float* nfb   = (const float*)d_in[14];
    const float* decw  = (const float*)d_in[15];
    const float* decb  = (const float*)d_in[16];
    float* out = (float*)d_out;

    float *p_ln, *p_lnf, *p_xz, *p_xc, *p_xdbl, *p_yg, *p_hidden;
    cudaGetSymbolAddress((void**)&p_ln,     g_ln);
    cudaGetSymbolAddress((void**)&p_lnf,    g_lnf);
    cudaGetSymbolAddress((void**)&p_xz,     g_xz);
    cudaGetSymbolAddress((void**)&p_xc,     g_xc);
    cudaGetSymbolAddress((void**)&p_xdbl,   g_xdbl);
    cudaGetSymbolAddress((void**)&p_yg,     g_yg);
    cudaGetSymbolAddress((void**)&p_hidden, g_hidden);

    k_embed<<<MR_*64/256, 256>>>(ids, emb);
    for(int i=0;i<NL_;i++){
        k_ln<<<MR_/8, 256>>>(nw + i*DM_, nb + i*DM_, p_ln, (i>0) ? 1 : 0);
        k_gemm<<<dim3(8,32), 256>>>(p_ln, inw + (size_t)i*2*DI_*DM_, p_xz, MR_, 2*DI_, DM_);
        k_conv<<<MR_*DI_/256, 256>>>(cw + i*DI_*4, cb + i*DI_);
        k_gemm<<<dim3(1,32), 256>>>(p_xc, xpw + (size_t)i*48*DI_, p_xdbl, MR_, 48, DI_);
        k_dt<<<dim3(MR_,4), 128>>>(dtw + (size_t)i*DI_*16, dtb + i*DI_);
        k_scan1<<<B_*NC_*DI_/256, 256>>>(Alog + (size_t)i*DI_*NS_);
        k_scan2<<<B_*DI_*NS_/256, 256>>>();
        k_scan3<<<B_*NC_*DI_/256, 256>>>(Alog + (size_t)i*DI_*NS_, Dp + i*DI_);
        k_gemm<<<dim3(2,32), 256>>>(p_yg, outw + (size_t)i*DM_*DI_, p_hidden, MR_, DM_, DI_);
    }
    k_ln<<<MR_/8, 256>>>(nfw, nfb, p_lnf, 1);
    k_pool1<<<B_*32*DM_/256, 256>>>();
    k_pool2<<<B_, 256>>>(decw, decb, out);
}

// round 3
// speedup vs baseline: 1.1916x; 1.1916x over previous
#include <cuda_runtime.h>
#include <cuda_bf16.h>
#include <cstdint>

#define B_   2
#define L_   2048
#define DM_  256
#define DI_  512
#define NS_  16
#define NL_  4
#define DO_  10
#define MR_  (B_*L_)          // 4096 rows
#define NC_  64               // scan chunks
#define CL_  (L_/NC_)         // 32 per chunk

// ---------------- scratch (static device memory; no allocations) ----------------
__device__ __align__(16) float g_resid [MR_*DM_];
__device__ __align__(16) float g_ln    [MR_*DM_];
__device__ __align__(16) float g_lnf   [MR_*DM_];
__device__ __align__(16) float g_xz    [MR_*2*DI_];
__device__ __align__(16) float g_xc    [MR_*DI_];
__device__ __align__(16) float g_xdbl  [MR_*48];
__device__ __align__(16) float g_yg    [MR_*DI_];
__device__ __align__(16) float g_P     [B_*NC_*DI_*NS_];
__device__ __align__(16) float g_hend  [B_*NC_*DI_*NS_];
__device__ __align__(16) float g_hin   [B_*NC_*DI_*NS_];
__device__ __align__(16) float g_part  [B_*32*DM_];

__device__ __forceinline__ float fex2(float x){ float r; asm("ex2.approx.f32 %0, %1;" : "=f"(r) : "f"(x)); return r; }
__device__ __forceinline__ float fexp(float x){ return fex2(x*1.44269504f); }
__device__ __forceinline__ float softplusf(float s){
    float e = fexp(s);
    return (s > 15.f) ? s : log1pf(e);
}
__device__ __forceinline__ void cpa16(void* dst, const void* src, int sz){
    unsigned s = (unsigned)__cvta_generic_to_shared(dst);
    asm volatile("cp.async.cg.shared.global [%0], [%1], 16, %2;" :: "r"(s), "l"(src), "r"(sz));
}
__device__ __forceinline__ void cp_commit(){ asm volatile("cp.async.commit_group;"); }
__device__ __forceinline__ void cp_wait0(){ asm volatile("cp.async.wait_group 0;"); }
__device__ __forceinline__ void cp_wait1(){ asm volatile("cp.async.wait_group 1;"); }

// ---------------- embedding gather + LayerNorm(layer0) ----------------
__global__ void k_embed_ln(const int* __restrict__ ids, const float* __restrict__ emb,
                           const float* __restrict__ w, const float* __restrict__ b){
    int row  = blockIdx.x*8 + (threadIdx.x>>5);
    int lane = threadIdx.x & 31;
    int id = ids[row];
    float4 a0 = *(const float4*)(emb + (size_t)id*DM_ + lane*4);
    float4 a1 = *(const float4*)(emb + (size_t)id*DM_ + lane*4 + 128);
    *(float4*)(g_resid + (size_t)row*DM_ + lane*4)       = a0;
    *(float4*)(g_resid + (size_t)row*DM_ + lane*4 + 128) = a1;
    float s = a0.x+a0.y+a0.z+a0.w+a1.x+a1.y+a1.z+a1.w;
    #pragma unroll
    for(int o=16;o;o>>=1) s += __shfl_xor_sync(0xffffffffu, s, o);
    float mean = s * (1.f/DM_);
    float q = 0.f;
    q += (a0.x-mean)*(a0.x-mean); q += (a0.y-mean)*(a0.y-mean);
    q += (a0.z-mean)*(a0.z-mean); q += (a0.w-mean)*(a0.w-mean);
    q += (a1.x-mean)*(a1.x-mean); q += (a1.y-mean)*(a1.y-mean);
    q += (a1.z-mean)*(a1.z-mean); q += (a1.w-mean)*(a1.w-mean);
    #pragma unroll
    for(int o=16;o;o>>=1) q += __shfl_xor_sync(0xffffffffu, q, o);
    float rs = rsqrtf(q*(1.f/DM_) + 1e-5f);
    float4 w0 = *(const float4*)(w + lane*4), w1 = *(const float4*)(w + lane*4 + 128);
    float4 b0 = *(const float4*)(b + lane*4), b1 = *(const float4*)(b + lane*4 + 128);
    float4 o0, o1;
    o0.x=(a0.x-mean)*rs*w0.x+b0.x; o0.y=(a0.y-mean)*rs*w0.y+b0.y;
    o0.z=(a0.z-mean)*rs*w0.z+b0.z; o0.w=(a0.w-mean)*rs*w0.w+b0.w;
    o1.x=(a1.x-mean)*rs*w1.x+b1.x; o1.y=(a1.y-mean)*rs*w1.y+b1.y;
    o1.z=(a1.z-mean)*rs*w1.z+b1.z; o1.w=(a1.w-mean)*rs*w1.w+b1.w;
    *(float4*)(g_ln + (size_t)row*DM_ + lane*4)       = o0;
    *(float4*)(g_ln + (size_t)row*DM_ + lane*4 + 128) = o1;
}

// ---------------- tf32 pipelined GEMM: C[M,N] = A[M,K] * W[N,K]^T ----------------
// BN=128, BK=16, 2-stage cp.async, 256 threads (8 warps = 2m x 4n)
template<int BM>
__global__ void __launch_bounds__(256) k_gemmp(const float* __restrict__ A,
                                               const float* __restrict__ W,
                                               float* __restrict__ C,
                                               int M, int N, int K){
    constexpr int MT = BM/32;
    __shared__ float As[2][BM][20];
    __shared__ float Bs[2][128][20];
    const int bm = blockIdx.y*BM, bn = blockIdx.x*128;
    const int tid = threadIdx.x, lane = tid&31, wid = tid>>5;
    const int wm = (wid&1)*(BM/2), wn = (wid>>1)*32;
    const int g = lane>>2, t4 = lane&3;
    float acc[MT][4][4] = {};

    auto loadA = [&](int st, int k0){
        #pragma unroll
        for(int i=0;i<(BM*4+255)/256;i++){
            int idx = tid + i*256;
            if((BM*4)%256==0 || idx < BM*4){
                int r = idx>>2, c4 = (idx&3)*4;
                cpa16(&As[st][r][c4], A + (size_t)(bm+r)*K + k0 + c4, 16);
            }
        }
    };
    auto loadB = [&](int st, int k0){
        #pragma unroll
        for(int i=0;i<2;i++){
            int idx = tid + i*256;
            int r = idx>>2, c4 = (idx&3)*4;
            int p = (bn+r < N) ? 16 : 0;
            const float* src = W + (size_t)(p ? (bn+r) : 0)*K + k0 + c4;
            cpa16(&Bs[st][r][c4], src, p);
        }
    };

    const int KT = K/16;
    loadA(0,0); loadB(0,0); cp_commit();
    for(int kt=0; kt<KT; kt++){
        if(kt+1 < KT){
            loadA((kt+1)&1, (kt+1)*16);
            loadB((kt+1)&1, (kt+1)*16);
            cp_commit();
            cp_wait1();
        } else {
            cp_wait0();
        }
        __syncthreads();
        int st = kt&1;
        #pragma unroll
        for(int ks=0;ks<2;ks++){
            const int kk = ks*8;
            unsigned a[MT][4], bf[4][2];
            #pragma unroll
            for(int mt=0;mt<MT;mt++){
                int r0 = wm + mt*16 + g;
                a[mt][0] = __float_as_uint(As[st][r0  ][kk+t4  ]);
                a[mt][1] = __float_as_uint(As[st][r0+8][kk+t4  ]);
                a[mt][2] = __float_as_uint(As[st][r0  ][kk+t4+4]);
                a[mt][3] = __float_as_uint(As[st][r0+8][kk+t4+4]);
            }
            #pragma unroll
            for(int nt=0;nt<4;nt++){
                int c0 = wn + nt*8 + g;
                bf[nt][0] = __float_as_uint(Bs[st][c0][kk+t4  ]);
                bf[nt][1] = __float_as_uint(Bs[st][c0][kk+t4+4]);
            }
            #pragma unroll
            for(int mt=0;mt<MT;mt++)
                #pragma unroll
                for(int nt=0;nt<4;nt++){
                    asm volatile("mma.sync.aligned.m16n8k8.row.col.f32.tf32.tf32.f32 "
                        "{%0,%1,%2,%3}, {%4,%5,%6,%7}, {%8,%9}, {%0,%1,%2,%3};"
                        : "+f"(acc[mt][nt][0]), "+f"(acc[mt][nt][1]),
                          "+f"(acc[mt][nt][2]), "+f"(acc[mt][nt][3])
                        : "r"(a[mt][0]),"r"(a[mt][1]),"r"(a[mt][2]),"r"(a[mt][3]),
                          "r"(bf[nt][0]),"r"(bf[nt][1]));
                }
        }
        __syncthreads();
    }
    #pragma unroll
    for(int mt=0;mt<MT;mt++){
        int r0 = bm + wm + mt*16 + g;
        #pragma unroll
        for(int nt=0;nt<4;nt++){
            int c0 = bn + wn + nt*8 + t4*2;
            if(c0 < N){
                *(float2*)(C + (size_t)r0*N + c0)     = make_float2(acc[mt][nt][0], acc[mt][nt][1]);
                *(float2*)(C + (size_t)(r0+8)*N + c0) = make_float2(acc[mt][nt][2], acc[mt][nt][3]);
            }
        }
    }
}

// ---------------- out_proj GEMM + residual add + LayerNorm (fused) ----------------
// BM=64, BN=256(full DM), BK=8, 2-stage cp.async, 256 threads (8 warps = 2m x 4n)
__global__ void __launch_bounds__(256) k_out_ln(const float* __restrict__ A,
                                                const float* __restrict__ W,
                                                const float* __restrict__ lw,
                                                const float* __restrict__ lb,
                                                float* __restrict__ dst){
    __shared__ float As[2][64][12];
    __shared__ float Bs[2][256][12];
    __shared__ float rsum[64][4], rsq[64][4];
    __shared__ float smean[64], srstd[64];
    const int K = DI_, N = DM_;
    const int bm = blockIdx.x*64;
    const int tid = threadIdx.x, lane = tid&31, wid = tid>>5;
    const int wm = (wid&1)*32, wn = (wid>>1)*64, nw = wid>>1;
    const int g = lane>>2, t4 = lane&3;
    float acc[2][8][4] = {};

    auto loadA = [&](int st, int k0){
        if(tid < 128){
            int r = tid>>1, c4 = (tid&1)*4;
            cpa16(&As[st][r][c4], A + (size_t)(bm+r)*K + k0 + c4, 16);
        }
    };
    auto loadB = [&](int st, int k0){
        #pragma unroll
        for(int i=0;i<2;i++){
            int idx = tid + i*256;
            int r = idx>>1, c4 = (idx&1)*4;
            cpa16(&Bs[st][r][c4], W + (size_t)r*K + k0 + c4, 16);
        }
    };

    const int KT = K/8;   // 64
    loadA(0,0); loadB(0,0); cp_commit();
    for(int kt=0; kt<KT; kt++){
        if(kt+1 < KT){
            loadA((kt+1)&1, (kt+1)*8);
            loadB((kt+1)&1, (kt+1)*8);
            cp_commit();
            cp_wait1();
        } else {
            cp_wait0();
        }
        __syncthreads();
        int st = kt&1;
        unsigned a[2][4], bf[8][2];
        #pragma unroll
        for(int mt=0;mt<2;mt++){
            int r0 = wm + mt*16 + g;
            a[mt][0] = __float_as_uint(As[st][r0  ][t4  ]);
            a[mt][1] = __float_as_uint(As[st][r0+8][t4  ]);
            a[mt][2] = __float_as_uint(As[st][r0  ][t4+4]);
            a[mt][3] = __float_as_uint(As[st][r0+8][t4+4]);
        }
        #pragma unroll
        for(int nt=0;nt<8;nt++){
            int c0 = wn + nt*8 + g;
            bf[nt][0] = __float_as_uint(Bs[st][c0][t4  ]);
            bf[nt][1] = __float_as_uint(Bs[st][c0][t4+4]);
        }
        #pragma unroll
        for(int mt=0;mt<2;mt++)
            #pragma unroll
            for(int nt=0;nt<8;nt++){
                asm volatile("mma.sync.aligned.m16n8k8.row.col.f32.tf32.tf32.f32 "
                    "{%0,%1,%2,%3}, {%4,%5,%6,%7}, {%8,%9}, {%0,%1,%2,%3};"
                    : "+f"(acc[mt][nt][0]), "+f"(acc[mt][nt][1]),
                      "+f"(acc[mt][nt][2]), "+f"(acc[mt][nt][3])
                    : "r"(a[mt][0]),"r"(a[mt][1]),"r"(a[mt][2]),"r"(a[mt][3]),
                      "r"(bf[nt][0]),"r"(bf[nt][1]));
            }
        __syncthreads();
    }

    // epilogue: resid_new = resid + acc; write resid; block-wide row LN; write ln
    float rn[2][8][4];
    #pragma unroll
    for(int mt=0;mt<2;mt++){
        int r0 = bm + wm + mt*16 + g;
        #pragma unroll
        for(int nt=0;nt<8;nt++){
            int c0 = wn + nt*8 + t4*2;
            float2 v0 = *(float2*)(g_resid + (size_t)r0*DM_ + c0);
            float2 v1 = *(float2*)(g_resid + (size_t)(r0+8)*DM_ + c0);
            rn[mt][nt][0] = v0.x + acc[mt][nt][0];
            rn[mt][nt][1] = v0.y + acc[mt][nt][1];
            rn[mt][nt][2] = v1.x + acc[mt][nt][2];
            rn[mt][nt][3] = v1.y + acc[mt][nt][3];
            *(float2*)(g_resid + (size_t)r0*DM_ + c0)     = make_float2(rn[mt][nt][0], rn[mt][nt][1]);
            *(float2*)(g_resid + (size_t)(r0+8)*DM_ + c0) = make_float2(rn[mt][nt][2], rn[mt][nt][3]);
        }
    }
    #pragma unroll
    for(int mt=0;mt<2;mt++){
        float s0=0.f,q0=0.f,s1=0.f,q1=0.f;
        #pragma unroll
        for(int nt=0;nt<8;nt++){
            s0 += rn[mt][nt][0] + rn[mt][nt][1];
            q0 += rn[mt][nt][0]*rn[mt][nt][0] + rn[mt][nt][1]*rn[mt][nt][1];
            s1 += rn[mt][nt][2] + rn[mt][nt][3];
            q1 += rn[mt][nt][2]*rn[mt][nt][2] + rn[mt][nt][3]*rn[mt][nt][3];
        }
        s0 += __shfl_xor_sync(0xffffffffu, s0, 1); s0 += __shfl_xor_sync(0xffffffffu, s0, 2);
        q0 += __shfl_xor_sync(0xffffffffu, q0, 1); q0 += __shfl_xor_sync(0xffffffffu, q0, 2);
        s1 += __shfl_xor_sync(0xffffffffu, s1, 1); s1 += __shfl_xor_sync(0xffffffffu, s1, 2);
        q1 += __shfl_xor_sync(0xffffffffu, q1, 1); q1 += __shfl_xor_sync(0xffffffffu, q1, 2);
        if(t4==0){
            int rr = wm + mt*16 + g;
            rsum[rr][nw] = s0;  rsq[rr][nw] = q0;
            rsum[rr+8][nw] = s1; rsq[rr+8][nw] = q1;
        }
    }
    __syncthreads();
    if(tid < 64){
        float s = rsum[tid][0]+rsum[tid][1]+rsum[tid][2]+rsum[tid][3];
        float q = rsq[tid][0]+rsq[tid][1]+rsq[tid][2]+rsq[tid][3];
        float mean = s * (1.f/DM_);
        float var  = q * (1.f/DM_) - mean*mean;
        smean[tid] = mean;
        srstd[tid] = rsqrtf(var + 1e-5f);
    }
    __syncthreads();
    #pragma unroll
    for(int mt=0;mt<2;mt++){
        int rr = wm + mt*16 + g;
        float m0 = smean[rr],   rs0 = srstd[rr];
        float m1 = smean[rr+8], rs1 = srstd[rr+8];
        int r0 = bm + rr;
        #pragma unroll
        for(int nt=0;nt<8;nt++){
            int c0 = wn + nt*8 + t4*2;
            float2 wv = *(const float2*)(lw + c0);
            float2 bv = *(const float2*)(lb + c0);
            float2 o0, o1;
            o0.x = (rn[mt][nt][0]-m0)*rs0*wv.x + bv.x;
            o0.y = (rn[mt][nt][1]-m0)*rs0*wv.y + bv.y;
            o1.x = (rn[mt][nt][2]-m1)*rs1*wv.x + bv.x;
            o1.y = (rn[mt][nt][3]-m1)*rs1*wv.y + bv.y;
            *(float2*)(dst + (size_t)r0*DM_ + c0)     = o0;
            *(float2*)(dst + (size_t)(r0+8)*DM_ + c0) = o1;
        }
    }
}

// ---------------- causal depthwise conv (K=4) + silu, 8 l per thread ----------------
__global__ void k_conv(const float* __restrict__ cw, const float* __restrict__ cb){
    int idx = blockIdx.x*blockDim.x + threadIdx.x;   // MR_*DI_/8 threads
    int d  = idx & (DI_-1);
    int mc = idx >> 9;
    int m0 = mc*8;
    int l0 = m0 & (L_-1);
    float4 w = *(const float4*)(cw + d*4);
    float bv = cb[d];
    float xw[11];
    #pragma unroll
    for(int j=0;j<11;j++){
        int lj = l0 - 3 + j;
        xw[j] = (lj >= 0) ? g_xz[(size_t)(m0-3+j)*2*DI_ + d] : 0.f;
    }
    #pragma unroll
    for(int j=0;j<8;j++){
        float s = bv + w.x*xw[j] + w.y*xw[j+1] + w.z*xw[j+2] + w.w*xw[j+3];
        float sig = 1.f/(1.f+fexp(-s));
        g_xc[(size_t)(m0+j)*DI_ + d] = s*sig;
    }
}

// ---------------- scan pass 1: chunk-local scan (h0=0) -> hend, P ----------------
__global__ void __launch_bounds__(256) k_scan1(const float* __restrict__ Alog,
                                               const float* __restrict__ dtw,
                                               const float* __restrict__ dtb){
    int idx = blockIdx.x*256 + threadIdx.x;          // B_*NC_*DI_ = 65536
    int d = idx & (DI_-1);
    int c = (idx >> 9) & (NC_-1);
    int b = idx >> 15;
    float An[NS_];
    #pragma unroll
    for(int i=0;i<NS_/4;i++){
        float4 v = *(const float4*)(Alog + (size_t)d*NS_ + i*4);
        An[i*4+0] = -fexp(v.x)*1.44269504f;
        An[i*4+1] = -fexp(v.y)*1.44269504f;
        An[i*4+2] = -fexp(v.z)*1.44269504f;
        An[i*4+3] = -fexp(v.w)*1.44269504f;
    }
    float wd[16];
    #pragma unroll
    for(int i=0;i<4;i++){
        float4 v = *(const float4*)(dtw + (size_t)d*16 + i*4);
        wd[i*4]=v.x; wd[i*4+1]=v.y; wd[i*4+2]=v.z; wd[i*4+3]=v.w;
    }
    float bd = dtb[d];
    float h[NS_];
    #pragma unroll
    for(int n=0;n<NS_;n++) h[n]=0.f;
    float S = 0.f;
    int row0 = b*L_ + c*CL_;
    #pragma unroll 4
    for(int l=0;l<CL_;l++){
        int row = row0 + l;
        const float* xd = g_xdbl + (size_t)row*48;
        float4 t0=*(const float4*)(xd),    t1=*(const float4*)(xd+4);
        float4 t2=*(const float4*)(xd+8),  t3=*(const float4*)(xd+12);
        float4 B0=*(const float4*)(xd+16), B1=*(const float4*)(xd+20);
        float4 B2=*(const float4*)(xd+24), B3=*(const float4*)(xd+28);
        float s = bd;
        s += t0.x*wd[0]+t0.y*wd[1]+t0.z*wd[2]+t0.w*wd[3];
        s += t1.x*wd[4]+t1.y*wd[5]+t1.z*wd[6]+t1.w*wd[7];
        s += t2.x*wd[8]+t2.y*wd[9]+t2.z*wd[10]+t2.w*wd[11];
        s += t3.x*wd[12]+t3.y*wd[13]+t3.z*wd[14]+t3.w*wd[15];
        float sp = softplusf(s);
        float u = g_xc[(size_t)row*DI_ + d];
        S += sp;
        float du = sp*u;
        float Bv[16]={B0.x,B0.y,B0.z,B0.w,B1.x,B1.y,B1.z,B1.w,B2.x,B2.y,B2.z,B2.w,B3.x,B3.y,B3.z,B3.w};
        #pragma unroll
        for(int n=0;n<NS_;n++){
            float dA = fex2(sp*An[n]);
            h[n] = fmaf(dA, h[n], du*Bv[n]);
        }
    }
    int ob = ((b*NC_ + c)*DI_ + d)*NS_;
    #pragma unroll
    for(int i=0;i<4;i++){
        *(float4*)(g_hend + ob + i*4) = make_float4(h[i*4], h[i*4+1], h[i*4+2], h[i*4+3]);
        *(float4*)(g_P + ob + i*4)    = make_float4(fex2(S*An[i*4]),  fex2(S*An[i*4+1]),
                                                    fex2(S*An[i*4+2]), fex2(S*An[i*4+3]));
    }
}

// ---------------- scan pass 2: sequential combine over chunks ----------------
__global__ void k_scan2(){
    int idx = blockIdx.x*256 + threadIdx.x;          // B_*DI_*NS_ = 16384
    int base = idx & (DI_*NS_ - 1);
    int b = idx >> 13;
    float run = 0.f;
    #pragma unroll 4
    for(int c=0;c<NC_;c++){
        int o = ((b*NC_ + c)*DI_)*NS_ + base;
        g_hin[o] = run;
        run = g_P[o]*run + g_hend[o];
    }
}

// ---------------- scan pass 3: full scan (h0=h_in) + y + Dp*xc + silu(z) gate ----------------
__global__ void __launch_bounds__(256) k_scan3(const float* __restrict__ Alog,
                                               const float* __restrict__ dtw,
                                               const float* __restrict__ dtb,
                                               const float* __restrict__ Dp){
    int idx = blockIdx.x*256 + threadIdx.x;
    int d = idx & (DI_-1);
    int c = (idx >> 9) & (NC_-1);
    int b = idx >> 15;
    float An[NS_];
    #pragma unroll
    for(int i=0;i<NS_/4;i++){
        float4 v = *(const float4*)(Alog + (size_t)d*NS_ + i*4);
        An[i*4+0] = -fexp(v.x)*1.44269504f;
        An[i*4+1] = -fexp(v.y)*1.44269504f;
        An[i*4+2] = -fexp(v.z)*1.44269504f;
        An[i*4+3] = -fexp(v.w)*1.44269504f;
    }
    float wd[16];
    #pragma unroll
    for(int i=0;i<4;i++){
        float4 v = *(const float4*)(dtw + (size_t)d*16 + i*4);
        wd[i*4]=v.x; wd[i*4+1]=v.y; wd[i*4+2]=v.z; wd[i*4+3]=v.w;
    }
    float bd = dtb[d];
    float Dd = Dp[d];
    int ob = ((b*NC_ + c)*DI_ + d)*NS_;
    float h[NS_];
    #pragma unroll
    for(int i=0;i<4;i++){
        float4 v = *(const float4*)(g_hin + ob + i*4);
        h[i*4]=v.x; h[i*4+1]=v.y; h[i*4+2]=v.z; h[i*4+3]=v.w;
    }
    int row0 = b*L_ + c*CL_;
    #pragma unroll 4
    for(int l=0;l<CL_;l++){
        int row = row0 + l;
        const float* xd = g_xdbl + (size_t)row*48;
        float4 t0=*(const float4*)(xd),    t1=*(const float4*)(xd+4);
        float4 t2=*(const float4*)(xd+8),  t3=*(const float4*)(xd+12);
        float4 B0=*(const float4*)(xd+16), B1=*(const float4*)(xd+20);
        float4 B2=*(const float4*)(xd+24), B3=*(const float4*)(xd+28);
        float4 C0=*(const float4*)(xd+32), C1=*(const float4*)(xd+36);
        float4 C2=*(const float4*)(xd+40), C3=*(const float4*)(xd+44);
        float s = bd;
        s += t0.x*wd[0]+t0.y*wd[1]+t0.z*wd[2]+t0.w*wd[3];
        s += t1.x*wd[4]+t1.y*wd[5]+t1.z*wd[6]+t1.w*wd[7];
        s += t2.x*wd[8]+t2.y*wd[9]+t2.z*wd[10]+t2.w*wd[11];
        s += t3.x*wd[12]+t3.y*wd[13]+t3.z*wd[14]+t3.w*wd[15];
        float sp = softplusf(s);
        float u = g_xc[(size_t)row*DI_ + d];
        float z = g_xz[(size_t)row*2*DI_ + DI_ + d];
        float du = sp*u;
        float Bv[16]={B0.x,B0.y,B0.z,B0.w,B1.x,B1.y,B1.z,B1.w,B2.x,B2.y,B2.z,B2.w,B3.x,B3.y,B3.z,B3.w};
        float Cv[16]={C0.x,C0.y,C0.z,C0.w,C1.x,C1.y,C1.z,C1.w,C2.x,C2.y,C2.z,C2.w,C3.x,C3.y,C3.z,C3.w};
        float y = 0.f;
        #pragma unroll
        for(int n=0;n<NS_;n++){
            float dA = fex2(sp*An[n]);
            h[n] = fmaf(dA, h[n], du*Bv[n]);
            y = fmaf(h[n], Cv[n], y);
        }
        y += Dd*u;
        float sig = 1.f/(1.f+fexp(-z));
        g_yg[(size_t)row*DI_ + d] = y * z * sig;
    }
}

// ---------------- pooling + decode ----------------
__global__ void k_pool1(){
    int idx = blockIdx.x*256 + threadIdx.x;          // B_*32*DM_ = 16384
    int dm = idx & 255;
    int seg = (idx >> 8) & 31;
    int b = idx >> 13;
    float s = 0.f;
    #pragma unroll 8
    for(int j=0;j<64;j++)
        s += g_lnf[((size_t)(b*L_) + seg*64 + j)*DM_ + dm];
    g_part[idx] = s;
}

__global__ void k_pool2(const float* __restrict__ decw, const float* __restrict__ decb,
                        float* __restrict__ out){
    __shared__ float pool[DM_];
    int b = blockIdx.x;
    int tid = threadIdx.x;
    float s = 0.f;
    #pragma unroll
    for(int seg=0;seg<32;seg++) s += g_part[(b*32+seg)*256 + tid];
    pool[tid] = s * (1.f/L_);
    __syncthreads();
    if(tid < DO_){
        float o = decb[tid];
        for(int k=0;k<DM_;k++) o = fmaf(pool[k], decw[tid*DM_+k], o);
        out[b*DO_ + tid] = o;
    }
}

// ---------------- host ----------------
extern "C" void kernel_launch(void* const* d_in, const int* in_sizes, int n_in,
                              void* d_out, int out_size){
    const int*   ids   = (const int*)  d_in[0];
    const float* emb   = (const float*)d_in[1];
    const float* nw    = (const float*)d_in[2];
    const float* nb    = (const float*)d_in[3];
    const float* inw   = (const float*)d_in[4];
    const float* cw    = (const float*)d_in[5];
    const float* cb    = (const float*)d_in[6];
    const float* xpw   = (const float*)d_in[7];
    const float* dtw   = (const float*)d_in[8];
    const float* dtb   = (const float*)d_in[9];
    const float* Alog  = (const float*)d_in[10];
    const float* Dp    = (const float*)d_in[11];
    const float* outw  = (const float*)d_in[12];
    const float* nfw   = (const float*)d_in[13];
    const float* nfb   = (const float*)d_in[14];
    const float* decw  = (const float*)d_in[15];
    const float* decb  = (const float*)d_in[16];
    float* out = (float*)d_out;

    float *p_ln, *p_lnf, *p_xz, *p_xc, *p_xdbl, *p_yg;
    cudaGetSymbolAddress((void**)&p_ln,   g_ln);
    cudaGetSymbolAddress((void**)&p_lnf,  g_lnf);
    cudaGetSymbolAddress((void**)&p_xz,   g_xz);
    cudaGetSymbolAddress((void**)&p_xc,   g_xc);
    cudaGetSymbolAddress((void**)&p_xdbl, g_xdbl);
    cudaGetSymbolAddress((void**)&p_yg,   g_yg);

    k_embed_ln<<<MR_/8, 256>>>(ids, emb, nw, nb);
    for(int i=0;i<NL_;i++){
        k_gemmp<128><<<dim3(8,32), 256>>>(p_ln, inw + (size_t)i*2*DI_*DM_, p_xz, MR_, 2*DI_, DM_);
        k_conv<<<MR_*DI_/8/256, 256>>>(cw + i*DI_*4, cb + i*DI_);
        k_gemmp<32><<<dim3(1,128), 256>>>(p_xc, xpw + (size_t)i*48*DI_, p_xdbl, MR_, 48, DI_);
        k_scan1<<<B_*NC_*DI_/256, 256>>>(Alog + (size_t)i*DI_*NS_, dtw + (size_t)i*DI_*16, dtb + i*DI_);
        k_scan2<<<B_*DI_*NS_/256, 256>>>();
        k_scan3<<<B_*NC_*DI_/256, 256>>>(Alog + (size_t)i*DI_*NS_, dtw + (size_t)i*DI_*16,
                                         dtb + i*DI_, Dp + i*DI_);
        const float* lw = (i < NL_-1) ? (nw + (i+1)*DM_) : nfw;
        const float* lb = (i < NL_-1) ? (nb + (i+1)*DM_) : nfb;
        float* dst = (i < NL_-1) ? p_ln : p_lnf;
        k_out_ln<<<MR_/64, 256>>>(p_yg, outw + (size_t)i*DM_*DI_, lw, lb, dst);
    }
    k_pool1<<<B_*32*DM_/256, 256>>>();
    k_pool2<<<B_, 256>>>(decw, decb, out);
}